// round 8
// baseline (speedup 1.0000x reference)
#include <cuda_runtime.h>
#include <cstdint>

// Cost volume: out[b,d,h,w] = (1/C) * sum_c left[b,c,h,w] * right[b,c,h,w-d], 0 for w<d
// B=8, C=64, H=160, W=320, D=48.

#define BB 8
#define CC 64
#define HH 160
#define WW 320
#define DD 48

#define CK     8              // C-chunk per stage
#define NSTAGE (CC / CK)      // 8
#define PAD    48             // left zero-pad of right row
#define NT     160            // 4 d-groups (x12d) * 40 w-groups (x8w)

// Bank-conflict-free arithmetic swizzle: +4-float gap every 32 floats.
#define SW(i) ((i) + 4 * ((i) >> 5))
#define SLS  356
#define SRS  412
// smem: 2*8*(356+412)*4 = 49152 B = 48 KB exactly -> 3 CTAs/SM.

typedef unsigned long long ull;

__device__ __forceinline__ ull pk(float lo, float hi) {
    ull v; asm("mov.b64 %0, {%1, %2};" : "=l"(v) : "f"(lo), "f"(hi)); return v;
}
__device__ __forceinline__ void upk(ull v, float& lo, float& hi) {
    asm("mov.b64 {%0, %1}, %2;" : "=f"(lo), "=f"(hi) : "l"(v));
}
// odd pair (hi of a, lo of b)
__device__ __forceinline__ ull mkodd(ull a, ull b) {
    float a0, a1, b0, b1;
    upk(a, a0, a1);
    upk(b, b0, b1);
    return pk(a1, b0);
}
__device__ __forceinline__ void ffma2(ull& d, ull a, ull b) {
    asm("fma.rn.f32x2 %0, %1, %2, %0;" : "+l"(d) : "l"(a), "l"(b));
}
__device__ __forceinline__ void fmul2(ull& d, ull a) {
    asm("mul.rn.f32x2 %0, %0, %1;" : "+l"(d) : "l"(a));
}
__device__ __forceinline__ void cpasync16(void* dst_smem, const void* src) {
    uint32_t d = (uint32_t)__cvta_generic_to_shared(dst_smem);
    asm volatile("cp.async.cg.shared.global [%0], [%1], 16;" :: "r"(d), "l"(src) : "memory");
}

__global__ __launch_bounds__(NT, 3) void corvol_kernel(
    const float* __restrict__ left,
    const float* __restrict__ right,
    float* __restrict__ out)
{
    __shared__ __align__(16) float sL[2][CK][SLS];
    __shared__ __align__(16) float sR[2][CK][SRS];

    const int bh  = blockIdx.x;
    const int b   = bh / HH;
    const int h   = bh % HH;
    const int tid = threadIdx.x;

    const int dg = tid / 40;       // 0..3
    const int wg = tid % 40;       // 0..39
    const int d0 = dg * 12;
    const int w0 = wg * 8;

    const float* lb = left  + ((size_t)b * CC * HH + h) * WW;
    const float* rb = right + ((size_t)b * CC * HH + h) * WW;

    // Zero the right-pad region ONCE for both buffers (2*8*12 = 192 float4s).
    for (int i = tid; i < 2 * CK * (PAD / 4); i += NT) {
        const int buf = i / (CK * (PAD / 4));
        const int cc  = (i % (CK * (PAD / 4))) / (PAD / 4);
        const int v   = (i % (PAD / 4)) * 4;
        *(float4*)&sR[buf][cc][SW(v)] = make_float4(0.f, 0.f, 0.f, 0.f);
    }

    ull acc2[12][4];
    #pragma unroll
    for (int di = 0; di < 12; di++)
        #pragma unroll
        for (int j = 0; j < 4; j++)
            acc2[di][j] = 0ull;

    // r[k] = logical sR index q+k, q = PAD + w0 - d0 - 12 (multiple of 4, >= 0).
    // FMA (di,j) uses pair starting at r[2j - di + 12]:
    //   di even -> even pair u[j + 6 - di/2]; di odd -> odd pair o[j + (11-di)/2].
    const int q   = PAD + w0 - d0 - 12;
    const int lw0 = SW(w0);
    const int rq0 = SW(q);
    const int rq1 = SW(q + 4);
    const int rq2 = SW(q + 8);
    const int rq3 = SW(q + 12);
    const int rq4 = SW(q + 16);

    // ---- stage 0 copy ----
    #pragma unroll
    for (int i = tid; i < CK * (WW / 4); i += NT) {
        const int cc = i / (WW / 4);
        const int v  = (i % (WW / 4)) * 4;
        const size_t goff = (size_t)cc * (HH * WW) + v;
        cpasync16(&sL[0][cc][SW(v)],       lb + goff);
        cpasync16(&sR[0][cc][SW(PAD + v)], rb + goff);
    }
    asm volatile("cp.async.commit_group;" ::: "memory");

    for (int s = 0; s < NSTAGE; s++) {
        const int cur = s & 1;
        if (s + 1 < NSTAGE) {
            const int nxt = (s + 1) & 1;
            const int c0n = (s + 1) * CK;
            #pragma unroll
            for (int i = tid; i < CK * (WW / 4); i += NT) {
                const int cc = i / (WW / 4);
                const int v  = (i % (WW / 4)) * 4;
                const size_t goff = (size_t)(c0n + cc) * (HH * WW) + v;
                cpasync16(&sL[nxt][cc][SW(v)],       lb + goff);
                cpasync16(&sR[nxt][cc][SW(PAD + v)], rb + goff);
            }
            asm volatile("cp.async.commit_group;" ::: "memory");
            asm volatile("cp.async.wait_group 1;"  ::: "memory");
        } else {
            asm volatile("cp.async.wait_group 0;"  ::: "memory");
        }
        __syncthreads();

        #pragma unroll
        for (int cc = 0; cc < CK; cc++) {
            const float* lrow = &sL[cur][cc][0];
            const float* rrow = &sR[cur][cc][0];

            // Left pairs Lu[j] = (l[2j], l[2j+1]) — free via 128-bit LDS.
            ull Lu[4];
            {
                ulonglong2 t0 = *(const ulonglong2*)(lrow + lw0);
                ulonglong2 t1 = *(const ulonglong2*)(lrow + lw0 + 4);
                Lu[0] = t0.x; Lu[1] = t0.y; Lu[2] = t1.x; Lu[3] = t1.y;
            }
            // Right even pairs u[t] = (r[2t], r[2t+1]), t = 0..9 — free.
            ull u[10];
            {
                ulonglong2 t;
                t = *(const ulonglong2*)(rrow + rq0); u[0] = t.x; u[1] = t.y;
                t = *(const ulonglong2*)(rrow + rq1); u[2] = t.x; u[3] = t.y;
                t = *(const ulonglong2*)(rrow + rq2); u[4] = t.x; u[5] = t.y;
                t = *(const ulonglong2*)(rrow + rq3); u[6] = t.x; u[7] = t.y;
                t = *(const ulonglong2*)(rrow + rq4); u[8] = t.x; u[9] = t.y;
            }

            // Even di rows: operands all free.
            #pragma unroll
            for (int di = 0; di < 12; di += 2) {
                #pragma unroll
                for (int j = 0; j < 4; j++)
                    ffma2(acc2[di][j], Lu[j], u[j + 6 - di / 2]);
            }

            // Odd di rows: build each odd pair just-in-time, use it, retire it.
            // o[m] = (r[2m+1], r[2m+2]) feeds (di, j) with j + (11-di)/2 == m.
            #pragma unroll
            for (int m = 0; m <= 8; m++) {
                const ull om = mkodd(u[m], u[m + 1]);
                #pragma unroll
                for (int di = 1; di < 12; di += 2) {
                    const int j = m - (11 - di) / 2;
                    if (j >= 0 && j < 4)
                        ffma2(acc2[di][j], Lu[j], om);
                }
            }
        }
        __syncthreads();
    }

    const float inv  = 1.0f / (float)CC;
    const ull   inv2 = pk(inv, inv);
    #pragma unroll
    for (int di = 0; di < 12; di++) {
        #pragma unroll
        for (int j = 0; j < 4; j++) fmul2(acc2[di][j], inv2);
        float* op = out + (((size_t)b * DD + (d0 + di)) * HH + h) * WW + w0;
        *(float4*)op       = *(float4*)&acc2[di][0];
        *(float4*)(op + 4) = *(float4*)&acc2[di][2];
    }
}

extern "C" void kernel_launch(void* const* d_in, const int* in_sizes, int n_in,
                              void* d_out, int out_size)
{
    const float* left  = (const float*)d_in[0];
    const float* right = (const float*)d_in[1];
    float* out = (float*)d_out;
    corvol_kernel<<<BB * HH, NT>>>(left, right, out);
}

// round 9
// speedup vs baseline: 1.0007x; 1.0007x over previous
#include <cuda_runtime.h>
#include <cstdint>

// Cost volume: out[b,d,h,w] = (1/C) * sum_c left[b,c,h,w] * right[b,c,h,w-d], 0 for w<d
// B=8, C=64, H=160, W=320, D=48.

#define BB 8
#define CC 64
#define HH 160
#define WW 320
#define DD 48

#define CK     8              // C-chunk per stage
#define NSTAGE (CC / CK)      // 8
#define PAD    48             // left zero-pad of right row
#define NT     160            // 4 d-groups (x12d) * 40 w-groups (x8w)

// Bank-conflict-free arithmetic swizzle: +4-float gap every 32 floats.
#define SW(i) ((i) + 4 * ((i) >> 5))
#define SLS  356
#define SRS  412
// smem: 2*8*(356+412)*4 = 49152 B = 48 KB exactly -> 3 CTAs/SM.

typedef unsigned long long ull;

__device__ __forceinline__ ull pk(float lo, float hi) {
    ull v; asm("mov.b64 %0, {%1, %2};" : "=l"(v) : "f"(lo), "f"(hi)); return v;
}
__device__ __forceinline__ void upk(ull v, float& lo, float& hi) {
    asm("mov.b64 {%0, %1}, %2;" : "=f"(lo), "=f"(hi) : "l"(v));
}
// odd pair (hi of a, lo of b)
__device__ __forceinline__ ull mkodd(ull a, ull b) {
    float a0, a1, b0, b1;
    upk(a, a0, a1);
    upk(b, b0, b1);
    return pk(a1, b0);
}
__device__ __forceinline__ void ffma2(ull& d, ull a, ull b) {
    asm("fma.rn.f32x2 %0, %1, %2, %0;" : "+l"(d) : "l"(a), "l"(b));
}
__device__ __forceinline__ void fmul2(ull& d, ull a) {
    asm("mul.rn.f32x2 %0, %0, %1;" : "+l"(d) : "l"(a));
}
__device__ __forceinline__ void cpasync16(void* dst_smem, const void* src) {
    uint32_t d = (uint32_t)__cvta_generic_to_shared(dst_smem);
    asm volatile("cp.async.cg.shared.global [%0], [%1], 16;" :: "r"(d), "l"(src) : "memory");
}

__global__ __launch_bounds__(NT, 3) void corvol_kernel(
    const float* __restrict__ left,
    const float* __restrict__ right,
    float* __restrict__ out)
{
    __shared__ __align__(16) float sL[2][CK][SLS];
    __shared__ __align__(16) float sR[2][CK][SRS];

    const int bh  = blockIdx.x;
    const int b   = bh / HH;
    const int h   = bh % HH;
    const int tid = threadIdx.x;

    const int dg = tid / 40;       // 0..3
    const int wg = tid % 40;       // 0..39
    const int d0 = dg * 12;
    const int w0 = wg * 8;

    const float* lb = left  + ((size_t)b * CC * HH + h) * WW;
    const float* rb = right + ((size_t)b * CC * HH + h) * WW;

    // Zero the right-pad region ONCE for both buffers (2*8*12 = 192 float4s).
    for (int i = tid; i < 2 * CK * (PAD / 4); i += NT) {
        const int buf = i / (CK * (PAD / 4));
        const int cc  = (i % (CK * (PAD / 4))) / (PAD / 4);
        const int v   = (i % (PAD / 4)) * 4;
        *(float4*)&sR[buf][cc][SW(v)] = make_float4(0.f, 0.f, 0.f, 0.f);
    }

    ull acc2[12][4];
    #pragma unroll
    for (int di = 0; di < 12; di++)
        #pragma unroll
        for (int j = 0; j < 4; j++)
            acc2[di][j] = 0ull;

    // r[k] = logical sR index q+k, q = PAD + w0 - d0 - 12 (multiple of 4, >= 0).
    // FMA (di,j) uses pair starting at r[2j - di + 12]:
    //   di even -> even pair u[j + 6 - di/2]; di odd -> odd pair o[j + (11-di)/2].
    const int q   = PAD + w0 - d0 - 12;
    const int lw0 = SW(w0);
    const int rq0 = SW(q);
    const int rq1 = SW(q + 4);
    const int rq2 = SW(q + 8);
    const int rq3 = SW(q + 12);
    const int rq4 = SW(q + 16);

    // ---- stage 0 copy ----
    #pragma unroll
    for (int i = tid; i < CK * (WW / 4); i += NT) {
        const int cc = i / (WW / 4);
        const int v  = (i % (WW / 4)) * 4;
        const size_t goff = (size_t)cc * (HH * WW) + v;
        cpasync16(&sL[0][cc][SW(v)],       lb + goff);
        cpasync16(&sR[0][cc][SW(PAD + v)], rb + goff);
    }
    asm volatile("cp.async.commit_group;" ::: "memory");

    for (int s = 0; s < NSTAGE; s++) {
        const int cur = s & 1;
        if (s + 1 < NSTAGE) {
            const int nxt = (s + 1) & 1;
            const int c0n = (s + 1) * CK;
            #pragma unroll
            for (int i = tid; i < CK * (WW / 4); i += NT) {
                const int cc = i / (WW / 4);
                const int v  = (i % (WW / 4)) * 4;
                const size_t goff = (size_t)(c0n + cc) * (HH * WW) + v;
                cpasync16(&sL[nxt][cc][SW(v)],       lb + goff);
                cpasync16(&sR[nxt][cc][SW(PAD + v)], rb + goff);
            }
            asm volatile("cp.async.commit_group;" ::: "memory");
            asm volatile("cp.async.wait_group 1;"  ::: "memory");
        } else {
            asm volatile("cp.async.wait_group 0;"  ::: "memory");
        }
        __syncthreads();

        #pragma unroll
        for (int cc = 0; cc < CK; cc++) {
            const float* lrow = &sL[cur][cc][0];
            const float* rrow = &sR[cur][cc][0];

            // Left pairs Lu[j] = (l[2j], l[2j+1]) — free via 128-bit LDS.
            ull Lu[4];
            {
                ulonglong2 t0 = *(const ulonglong2*)(lrow + lw0);
                ulonglong2 t1 = *(const ulonglong2*)(lrow + lw0 + 4);
                Lu[0] = t0.x; Lu[1] = t0.y; Lu[2] = t1.x; Lu[3] = t1.y;
            }
            // Right even pairs u[t] = (r[2t], r[2t+1]), t = 0..9 — free.
            ull u[10];
            {
                ulonglong2 t;
                t = *(const ulonglong2*)(rrow + rq0); u[0] = t.x; u[1] = t.y;
                t = *(const ulonglong2*)(rrow + rq1); u[2] = t.x; u[3] = t.y;
                t = *(const ulonglong2*)(rrow + rq2); u[4] = t.x; u[5] = t.y;
                t = *(const ulonglong2*)(rrow + rq3); u[6] = t.x; u[7] = t.y;
                t = *(const ulonglong2*)(rrow + rq4); u[8] = t.x; u[9] = t.y;
            }

            // Even di rows: operands all free.
            #pragma unroll
            for (int di = 0; di < 12; di += 2) {
                #pragma unroll
                for (int j = 0; j < 4; j++)
                    ffma2(acc2[di][j], Lu[j], u[j + 6 - di / 2]);
            }

            // Odd di rows: build each odd pair just-in-time, use it, retire it.
            // o[m] = (r[2m+1], r[2m+2]) feeds (di, j) with j + (11-di)/2 == m.
            #pragma unroll
            for (int m = 0; m <= 8; m++) {
                const ull om = mkodd(u[m], u[m + 1]);
                #pragma unroll
                for (int di = 1; di < 12; di += 2) {
                    const int j = m - (11 - di) / 2;
                    if (j >= 0 && j < 4)
                        ffma2(acc2[di][j], Lu[j], om);
                }
            }
        }
        __syncthreads();
    }

    const float inv  = 1.0f / (float)CC;
    const ull   inv2 = pk(inv, inv);
    #pragma unroll
    for (int di = 0; di < 12; di++) {
        #pragma unroll
        for (int j = 0; j < 4; j++) fmul2(acc2[di][j], inv2);
        float* op = out + (((size_t)b * DD + (d0 + di)) * HH + h) * WW + w0;
        *(float4*)op       = *(float4*)&acc2[di][0];
        *(float4*)(op + 4) = *(float4*)&acc2[di][2];
    }
}

extern "C" void kernel_launch(void* const* d_in, const int* in_sizes, int n_in,
                              void* d_out, int out_size)
{
    const float* left  = (const float*)d_in[0];
    const float* right = (const float*)d_in[1];
    float* out = (float*)d_out;
    corvol_kernel<<<BB * HH, NT>>>(left, right, out);
}